// round 11
// baseline (speedup 1.0000x reference)
#include <cuda_runtime.h>
#include <math.h>

#define N_X      130
#define N_INT    128
#define BATCH    64
#define LATENT   8
#define HIDDEN   64
#define IN_DIM   12
#define STAB     0.1f
#define NEWTON_ITERS 4               // + 1 chord step = 5 effective iterations
#define GROUPS   8
#define JPT      (HIDDEN / GROUPS)   // 8 hidden units per thread
#define JP2      (JPT / 2)           // 4 packed pairs
#define NT       (N_INT * GROUPS)    // 1024 threads

typedef unsigned long long u64;
union F2U { float2 f; u64 u; };

__device__ __forceinline__ u64 pk2(float lo, float hi) {
    F2U t; t.f = make_float2(lo, hi); return t.u;
}
__device__ __forceinline__ float2 upk2(u64 v) { F2U t; t.u = v; return t.f; }
__device__ __forceinline__ u64 ldp(const float2* p) { F2U t; t.f = *p; return t.u; }

__device__ __forceinline__ u64 fma2(u64 a, u64 b, u64 c) {
    u64 d; asm("fma.rn.f32x2 %0, %1, %2, %3;" : "=l"(d) : "l"(a), "l"(b), "l"(c)); return d;
}
__device__ __forceinline__ u64 mul2(u64 a, u64 b) {
    u64 d; asm("mul.rn.f32x2 %0, %1, %2;" : "=l"(d) : "l"(a), "l"(b)); return d;
}
__device__ __forceinline__ float tanh_fast(float v) {
    float y; asm("tanh.approx.f32 %0, %1;" : "=f"(y) : "f"(v)); return y;
}
// MUFU-based near-exact tanh: 1 - 2/(exp(2x)+1). Abs err ~1e-7.
__device__ __forceinline__ float tanh_exact(float v) {
    const float e = __expf(2.0f * v);
    return 1.0f - __fdividef(2.0f, e + 1.0f);
}
__device__ __forceinline__ float frcp(float v) {
    float y; asm("rcp.approx.f32 %0, %1;" : "=f"(y) : "f"(v)); return y;
}
__device__ __forceinline__ void bar_pcr() {                 // warps 0-3 only
    asm volatile("bar.sync 1, 128;" ::: "memory");
}
__device__ __forceinline__ void bar_sync_id(int id) {
    asm volatile("bar.sync %0, %1;" :: "r"(id), "n"(NT) : "memory");
}
__device__ __forceinline__ void bar_arrive_id(int id) {
    asm volatile("bar.arrive %0, %1;" :: "r"(id), "n"(NT) : "memory");
}

__global__ void __launch_bounds__(NT, 1)
pde_newton_kernel(const float* __restrict__ u0,
                  const float* __restrict__ zb,
                  const float* __restrict__ x,
                  const float* __restrict__ W1,
                  const float* __restrict__ b1,
                  const float* __restrict__ W2,
                  const float* __restrict__ b2,
                  float* __restrict__ out)
{
    __shared__ float  W1s[IN_DIM * HIDDEN];
    __shared__ float  b1s[HIDDEN];
    __shared__ float  W2s[HIDDEN];
    __shared__ float  nW2s[HIDDEN];
    __shared__ float  zs[LATENT];
    __shared__ float  xs[N_X];
    __shared__ float  us[N_INT + 2];        // zero Dirichlet padding
    __shared__ float4 red[NT];              // MLP partial sums
    __shared__ float4 T[2][N_INT];          // tridiag rows / chord scalar buffer
    __shared__ float2 AB[6][N_INT];         // saved PCR multipliers (alpha,beta)
    __shared__ float2 KAB[N_INT];           // saved close coefficients
    __shared__ float  b2s;

    const int tid = threadIdx.x;
    const int bid = blockIdx.x;
    const int q   = tid & (N_INT - 1);
    const int L   = q & 31;                 // lane
    const int ws  = q >> 5;                 // subwarp 0..3
    const int i   = 4 * L + ws;             // permuted interior point
    const int g   = tid >> 7;               // hidden group 0..7 (warp-uniform)

    // ---- cooperative loads ----
    for (int k = tid; k < IN_DIM * HIDDEN; k += NT) W1s[k] = W1[k];
    if (tid < HIDDEN) { b1s[tid] = b1[tid]; W2s[tid] = W2[tid]; nW2s[tid] = -W2[tid]; }
    if (tid < LATENT) zs[tid] = zb[bid * LATENT + tid];
    if (tid < N_X)    xs[tid] = x[tid];
    if (tid == 0) { b2s = b2[0]; us[0] = 0.0f; us[N_INT + 1] = 0.0f; }
    if (tid < N_INT)  us[tid + 1] = u0[bid * N_INT + tid];
    __syncthreads();

    const float xi       = xs[i + 1];
    const float inv_dx2  = 1.0f / (xs[i + 2] - xs[i]);
    const float inv_hfhb = 1.0f / ((xs[i + 2] - xs[i + 1]) * (xs[i + 1] - xs[i]));

    const float2* __restrict__ W1u2  = (const float2*)(W1s + 1 * HIDDEN);
    const float2* __restrict__ W1x2  = (const float2*)(W1s + 2 * HIDDEN);
    const float2* __restrict__ W1xx2 = (const float2*)(W1s + 3 * HIDDEN);
    const float2* __restrict__ W2p   = (const float2*)W2s;
    const float2* __restrict__ nW2p  = (const float2*)nW2s;
    float* __restrict__ redf = (float*)red;
    float* __restrict__ Td   = (float*)T;

    // ---- iteration-invariant preactivation (packed) ----
    const int jp0 = g * JP2;
    u64 pre_c[JP2];
#pragma unroll
    for (int jj = 0; jj < JP2; jj++) {
        const int j = (jp0 + jj) * 2;
        float pc0 = fmaf(xi, W1s[j],     b1s[j]);
        float pc1 = fmaf(xi, W1s[j + 1], b1s[j + 1]);
#pragma unroll
        for (int k = 0; k < LATENT; k++) {
            pc0 = fmaf(zs[k], W1s[(4 + k) * HIDDEN + j],     pc0);
            pc1 = fmaf(zs[k], W1s[(4 + k) * HIDDEN + j + 1], pc1);
        }
        pre_c[jj] = pk2(pc0, pc1);
    }

    if (g == 0) {
        // ================= PCR / solver warps (tid 0..127) =================
#pragma unroll 1
        for (int iter = 0; iter < NEWTON_ITERS; iter++) {
            const float um  = us[i];
            const float uc  = us[i + 1];
            const float up  = us[i + 2];
            const float ux  = (up - um) * inv_dx2;
            const float uxx = (up - 2.0f * uc + um) * inv_hfhb;
            const u64 uc2  = pk2(uc,  uc);
            const u64 ux2  = pk2(ux,  ux);
            const u64 uxx2 = pk2(uxx, uxx);

            u64 a0 = 0ull, a1 = 0ull, a2 = 0ull, a3 = 0ull;
#pragma unroll
            for (int jj = 0; jj < JP2; jj++) {
                const int jp = jp0 + jj;
                const u64 w1u2  = ldp(W1u2  + jp);
                const u64 w1x2  = ldp(W1x2  + jp);
                const u64 w1xx2 = ldp(W1xx2 + jp);
                const u64 w22   = ldp(W2p   + jp);
                const u64 nw22  = ldp(nW2p  + jp);
                u64 pre = pre_c[jj];
                pre = fma2(uc2,  w1u2,  pre);
                pre = fma2(ux2,  w1x2,  pre);
                pre = fma2(uxx2, w1xx2, pre);
                const float2 pf = upk2(pre);
                const u64 t2 = pk2(tanh_fast(pf.x), tanh_fast(pf.y));
                a0 = fma2(t2, w22, a0);
                const u64 tsq = mul2(t2, t2);
                const u64 g2  = fma2(tsq, nw22, w22);
                a1 = fma2(g2, w1u2,  a1);
                a2 = fma2(g2, w1x2,  a2);
                a3 = fma2(g2, w1xx2, a3);
            }
            const float2 f0 = upk2(a0), f1 = upk2(a1), f2 = upk2(a2), f3 = upk2(a3);
            float acc_res  = f0.x + f0.y;
            float acc_du   = f1.x + f1.y;
            float acc_dux  = f2.x + f2.y;
            float acc_duxx = f3.x + f3.y;

            bar_sync_id(4);                        // wait partials from warps 4-31
#pragma unroll
            for (int k = 1; k < GROUPS; k++) {
                const float4 rk = red[q + 128 * k];
                acc_res  += rk.x;
                acc_du   += rk.y;
                acc_dux  += rk.z;
                acc_duxx += rk.w;
            }

            const float qq = (acc_duxx + STAB) * inv_hfhb;
            float4 m4;
            m4.x = (i == 0)         ? 0.0f : fmaf(-acc_dux, inv_dx2, qq);
            m4.y = acc_du - 2.0f * qq;
            m4.z = (i == N_INT - 1) ? 0.0f : fmaf( acc_dux, inv_dx2, qq);
            m4.w = acc_res + b2s + STAB * uxx;
            T[0][i] = m4;
            bar_pcr();

            // ---- shared PCR steps s=1,2 (multipliers saved for chord) ----
#pragma unroll
            for (int s = 1; s <= 2; s <<= 1) {
                float4 lo = make_float4(0.f, 1.f, 0.f, 0.f);
                float4 hi = make_float4(0.f, 1.f, 0.f, 0.f);
                if (i >= s)        lo = T[s - 1][i - s];
                if (i + s < N_INT) hi = T[s - 1][i + s];
                const float alpha = -__fdividef(m4.x, lo.y);
                const float beta  = -__fdividef(m4.z, hi.y);
                AB[s - 1][i] = make_float2(alpha, beta);
                float4 n;
                n.x = alpha * lo.x;
                n.y = fmaf(alpha, lo.z, fmaf(beta, hi.x, m4.y));
                n.z = beta * hi.z;
                n.w = fmaf(alpha, lo.w, fmaf(beta, hi.w, m4.w));
                m4 = n;
                if (s == 1) { T[1][i] = m4; bar_pcr(); }
            }

            // ---- shfl PCR steps (exact-zero edge invariant, no guards) ----
            int st = 2;
#pragma unroll
            for (int d = 1; d <= 8; d <<= 1, st++) {
                const float lox = __shfl_up_sync(0xffffffffu, m4.x, d);
                const float loy = __shfl_up_sync(0xffffffffu, m4.y, d);
                const float loz = __shfl_up_sync(0xffffffffu, m4.z, d);
                const float low = __shfl_up_sync(0xffffffffu, m4.w, d);
                const float hix = __shfl_down_sync(0xffffffffu, m4.x, d);
                const float hiy = __shfl_down_sync(0xffffffffu, m4.y, d);
                const float hiz = __shfl_down_sync(0xffffffffu, m4.z, d);
                const float hiw = __shfl_down_sync(0xffffffffu, m4.w, d);
                const float alpha = -__fdividef(m4.x, loy);
                const float beta  = -__fdividef(m4.z, hiy);
                AB[st][i] = make_float2(alpha, beta);
                float4 n;
                n.x = alpha * lox;
                n.y = fmaf(alpha, loz, fmaf(beta, hix, m4.y));
                n.z = beta * hiz;
                n.w = fmaf(alpha, low, fmaf(beta, hiw, m4.w));
                m4 = n;
            }

            // ---- close: 2x2 Cramer, coefficients saved for chord ----
            const float qx = __shfl_xor_sync(0xffffffffu, m4.x, 16);
            const float qy = __shfl_xor_sync(0xffffffffu, m4.y, 16);
            const float qz = __shfl_xor_sync(0xffffffffu, m4.z, 16);
            const float qw = __shfl_xor_sync(0xffffffffu, m4.w, 16);
            const float cc = (L < 16) ? m4.z : m4.x;
            const float qa = (L < 16) ? qx   : qz;
            const float den = fmaf(m4.y, qy, -cc * qa);
            const float inv = frcp(den);
            KAB[i] = make_float2(qy * inv, -cc * inv);
            const float xsol = fmaf(m4.w, qy, -cc * qw) * inv;
            us[i + 1] = uc - xsol;                           // DAMP = 1
            bar_pcr();                                       // us visible in warps 0-3
            bar_arrive_id(3);                                // release MLP warps
        }

        // ================= chord step: u5 = u4 - J(u3)^{-1} r(u4) ==========
        {
            const float um  = us[i];
            const float uc  = us[i + 1];
            const float up  = us[i + 2];
            const float ux  = (up - um) * inv_dx2;
            const float uxx = (up - 2.0f * uc + um) * inv_hfhb;
            const u64 uc2  = pk2(uc,  uc);
            const u64 ux2  = pk2(ux,  ux);
            const u64 uxx2 = pk2(uxx, uxx);

            u64 a0 = 0ull;                       // residual only, exact tanh
#pragma unroll
            for (int jj = 0; jj < JP2; jj++) {
                const int jp = jp0 + jj;
                u64 pre = pre_c[jj];
                pre = fma2(uc2,  ldp(W1u2  + jp), pre);
                pre = fma2(ux2,  ldp(W1x2  + jp), pre);
                pre = fma2(uxx2, ldp(W1xx2 + jp), pre);
                const float2 pf = upk2(pre);
                const u64 t2 = pk2(tanh_exact(pf.x), tanh_exact(pf.y));
                a0 = fma2(t2, ldp(W2p + jp), a0);
            }
            const float2 f0 = upk2(a0);
            float d = (f0.x + f0.y);

            bar_sync_id(4);                      // wait residual partials
#pragma unroll
            for (int k = 1; k < GROUPS; k++) d += redf[4 * (q + 128 * k)];
            d += b2s + STAB * uxx;               // r(u4)

            // ---- divide-free cascade through saved multipliers ----
            Td[i] = d; bar_pcr();
            {   const float2 ab = AB[0][i];
                const float dlo = (i >= 1)         ? Td[i - 1] : 0.0f;
                const float dhi = (i + 1 < N_INT)  ? Td[i + 1] : 0.0f;
                d = fmaf(ab.x, dlo, fmaf(ab.y, dhi, d));
                Td[N_INT + i] = d; bar_pcr(); }
            {   const float2 ab = AB[1][i];
                const float dlo = (i >= 2)         ? Td[N_INT + i - 2] : 0.0f;
                const float dhi = (i + 2 < N_INT)  ? Td[N_INT + i + 2] : 0.0f;
                d = fmaf(ab.x, dlo, fmaf(ab.y, dhi, d)); }
            int st = 2;
#pragma unroll
            for (int dd = 1; dd <= 8; dd <<= 1, st++) {
                const float2 ab = AB[st][i];
                const float dlo = __shfl_up_sync(0xffffffffu, d, dd);
                const float dhi = __shfl_down_sync(0xffffffffu, d, dd);
                d = fmaf(ab.x, dlo, fmaf(ab.y, dhi, d));
            }
            const float dq = __shfl_xor_sync(0xffffffffu, d, 16);
            const float2 k = KAB[i];
            out[bid * N_INT + i] = uc - fmaf(k.x, d, k.y * dq);
        }
    } else {
        // ================= MLP-only warps (tid 128..1023) ===================
#pragma unroll 1
        for (int iter = 0; iter < NEWTON_ITERS; iter++) {
            if (iter) bar_sync_id(3);            // wait updated us
            const float um  = us[i];
            const float uc  = us[i + 1];
            const float up  = us[i + 2];
            const float ux  = (up - um) * inv_dx2;
            const float uxx = (up - 2.0f * uc + um) * inv_hfhb;
            const u64 uc2  = pk2(uc,  uc);
            const u64 ux2  = pk2(ux,  ux);
            const u64 uxx2 = pk2(uxx, uxx);

            u64 a0 = 0ull, a1 = 0ull, a2 = 0ull, a3 = 0ull;
#pragma unroll
            for (int jj = 0; jj < JP2; jj++) {
                const int jp = jp0 + jj;
                const u64 w1u2  = ldp(W1u2  + jp);
                const u64 w1x2  = ldp(W1x2  + jp);
                const u64 w1xx2 = ldp(W1xx2 + jp);
                const u64 w22   = ldp(W2p   + jp);
                const u64 nw22  = ldp(nW2p  + jp);
                u64 pre = pre_c[jj];
                pre = fma2(uc2,  w1u2,  pre);
                pre = fma2(ux2,  w1x2,  pre);
                pre = fma2(uxx2, w1xx2, pre);
                const float2 pf = upk2(pre);
                const u64 t2 = pk2(tanh_fast(pf.x), tanh_fast(pf.y));
                a0 = fma2(t2, w22, a0);
                const u64 tsq = mul2(t2, t2);
                const u64 g2  = fma2(tsq, nw22, w22);
                a1 = fma2(g2, w1u2,  a1);
                a2 = fma2(g2, w1x2,  a2);
                a3 = fma2(g2, w1xx2, a3);
            }
            const float2 f0 = upk2(a0), f1 = upk2(a1), f2 = upk2(a2), f3 = upk2(a3);
            red[tid] = make_float4(f0.x + f0.y, f1.x + f1.y, f2.x + f2.y, f3.x + f3.y);
            bar_arrive_id(4);                    // release solver warps
        }
        // chord residual partial
        {
            bar_sync_id(3);
            const float um  = us[i];
            const float uc  = us[i + 1];
            const float up  = us[i + 2];
            const float ux  = (up - um) * inv_dx2;
            const float uxx = (up - 2.0f * uc + um) * inv_hfhb;
            const u64 uc2  = pk2(uc,  uc);
            const u64 ux2  = pk2(ux,  ux);
            const u64 uxx2 = pk2(uxx, uxx);
            u64 a0 = 0ull;
#pragma unroll
            for (int jj = 0; jj < JP2; jj++) {
                const int jp = jp0 + jj;
                u64 pre = pre_c[jj];
                pre = fma2(uc2,  ldp(W1u2  + jp), pre);
                pre = fma2(ux2,  ldp(W1x2  + jp), pre);
                pre = fma2(uxx2, ldp(W1xx2 + jp), pre);
                const float2 pf = upk2(pre);
                const u64 t2 = pk2(tanh_exact(pf.x), tanh_exact(pf.y));
                a0 = fma2(t2, ldp(W2p + jp), a0);
            }
            const float2 f0 = upk2(a0);
            redf[4 * tid] = f0.x + f0.y;
            bar_arrive_id(4);
        }
    }
}

extern "C" void kernel_launch(void* const* d_in, const int* in_sizes, int n_in,
                              void* d_out, int out_size)
{
    const float* u0 = (const float*)d_in[0];
    const float* zb = (const float*)d_in[1];
    const float* x  = (const float*)d_in[2];
    const float* W1 = (const float*)d_in[3];
    const float* b1 = (const float*)d_in[4];
    const float* W2 = (const float*)d_in[5];
    const float* b2 = (const float*)d_in[6];
    pde_newton_kernel<<<BATCH, NT>>>(u0, zb, x, W1, b1, W2, b2, (float*)d_out);
}

// round 12
// speedup vs baseline: 1.1575x; 1.1575x over previous
#include <cuda_runtime.h>
#include <math.h>

#define N_X      130
#define N_INT    128
#define BATCH    64
#define LATENT   8
#define HIDDEN   64
#define IN_DIM   12
#define STAB     0.1f
#define NEWTON_ITERS 4               // + 1 chord step = 5 effective iterations
#define GROUPS   4
#define JPT      (HIDDEN / GROUPS)   // 16 hidden units per thread
#define JP2      (JPT / 2)           // 8 packed pairs
#define NT       (N_INT * GROUPS)    // 512 threads

typedef unsigned long long u64;
union F2U { float2 f; u64 u; };

__device__ __forceinline__ u64 pk2(float lo, float hi) {
    F2U t; t.f = make_float2(lo, hi); return t.u;
}
__device__ __forceinline__ float2 upk2(u64 v) { F2U t; t.u = v; return t.f; }
__device__ __forceinline__ u64 ldp(const float2* p) { F2U t; t.f = *p; return t.u; }

__device__ __forceinline__ u64 fma2(u64 a, u64 b, u64 c) {
    u64 d; asm("fma.rn.f32x2 %0, %1, %2, %3;" : "=l"(d) : "l"(a), "l"(b), "l"(c)); return d;
}
__device__ __forceinline__ u64 mul2(u64 a, u64 b) {
    u64 d; asm("mul.rn.f32x2 %0, %1, %2;" : "=l"(d) : "l"(a), "l"(b)); return d;
}
__device__ __forceinline__ float tanh_fast(float v) {
    float y; asm("tanh.approx.f32 %0, %1;" : "=f"(y) : "f"(v)); return y;
}
__device__ __forceinline__ float frcp(float v) {
    float y; asm("rcp.approx.f32 %0, %1;" : "=f"(y) : "f"(v)); return y;
}
__device__ __forceinline__ void bar_pcr() {                 // warps 0-3 only
    asm volatile("bar.sync 1, 128;" ::: "memory");
}
__device__ __forceinline__ void bar_sync_id(int id) {
    asm volatile("bar.sync %0, %1;" :: "r"(id), "n"(NT) : "memory");
}
__device__ __forceinline__ void bar_arrive_id(int id) {
    asm volatile("bar.arrive %0, %1;" :: "r"(id), "n"(NT) : "memory");
}

__global__ void __launch_bounds__(NT, 1)
pde_newton_kernel(const float* __restrict__ u0,
                  const float* __restrict__ zb,
                  const float* __restrict__ x,
                  const float* __restrict__ W1,
                  const float* __restrict__ b1,
                  const float* __restrict__ W2,
                  const float* __restrict__ b2,
                  float* __restrict__ out)
{
    __shared__ float  W1s[IN_DIM * HIDDEN];
    __shared__ float  b1s[HIDDEN];
    __shared__ float  W2s[HIDDEN];
    __shared__ float  nW2s[HIDDEN];
    __shared__ float  zs[LATENT];
    __shared__ float  xs[N_X];
    __shared__ float  us[N_INT + 2];        // zero Dirichlet padding
    __shared__ float4 red[NT];              // MLP partial sums
    __shared__ float4 T[2][N_INT];          // PCR payload (a, rb, c, d) / chord buffer
    __shared__ float2 AB[6][N_INT];         // saved PCR multipliers (alpha,beta)
    __shared__ float2 KAB[N_INT];           // saved close coefficients
    __shared__ float  b2s;

    const int tid = threadIdx.x;
    const int bid = blockIdx.x;
    const int q   = tid & (N_INT - 1);
    const int L   = q & 31;                 // lane
    const int ws  = q >> 5;                 // subwarp 0..3
    const int i   = 4 * L + ws;             // permuted interior point
    const int g   = tid >> 7;               // hidden group 0..3 (warp-uniform)

    // ---- cooperative loads (W1 as float4) ----
    if (tid < (IN_DIM * HIDDEN) / 4)
        ((float4*)W1s)[tid] = ((const float4*)W1)[tid];
    if (tid < HIDDEN) { b1s[tid] = b1[tid]; W2s[tid] = W2[tid]; nW2s[tid] = -W2[tid]; }
    if (tid < LATENT) zs[tid] = zb[bid * LATENT + tid];
    if (tid < N_X)    xs[tid] = x[tid];
    if (tid == 0) { b2s = b2[0]; us[0] = 0.0f; us[N_INT + 1] = 0.0f; }
    if (tid < N_INT)  us[tid + 1] = u0[bid * N_INT + tid];
    __syncthreads();

    const float xi       = xs[i + 1];
    const float inv_dx2  = 1.0f / (xs[i + 2] - xs[i]);
    const float inv_hfhb = 1.0f / ((xs[i + 2] - xs[i + 1]) * (xs[i + 1] - xs[i]));

    const float2* __restrict__ W1u2  = (const float2*)(W1s + 1 * HIDDEN);
    const float2* __restrict__ W1x2  = (const float2*)(W1s + 2 * HIDDEN);
    const float2* __restrict__ W1xx2 = (const float2*)(W1s + 3 * HIDDEN);
    const float2* __restrict__ W2p   = (const float2*)W2s;
    const float2* __restrict__ nW2p  = (const float2*)nW2s;
    float* __restrict__ redf = (float*)red;
    float* __restrict__ Td   = (float*)T;

    // ---- iteration-invariant preactivation (packed f32x2) ----
    const int jp0 = g * JP2;
    const u64 xi2 = pk2(xi, xi);
    u64 pre_c[JP2];
#pragma unroll
    for (int jj = 0; jj < JP2; jj++)
        pre_c[jj] = fma2(xi2, ldp((const float2*)W1s + jp0 + jj),
                              ldp((const float2*)b1s + jp0 + jj));
#pragma unroll
    for (int k = 0; k < LATENT; k++) {
        const u64 zk2 = pk2(zs[k], zs[k]);
        const float2* Wk = (const float2*)(W1s + (4 + k) * HIDDEN);
#pragma unroll
        for (int jj = 0; jj < JP2; jj++)
            pre_c[jj] = fma2(zk2, ldp(Wk + jp0 + jj), pre_c[jj]);
    }

    if (g == 0) {
        // ================= PCR / solver warps (tid 0..127) =================
#pragma unroll 1
        for (int iter = 0; iter < NEWTON_ITERS; iter++) {
            const float um  = us[i];
            const float uc  = us[i + 1];
            const float up  = us[i + 2];
            const float ux  = (up - um) * inv_dx2;
            const float uxx = (up - 2.0f * uc + um) * inv_hfhb;
            const u64 uc2  = pk2(uc,  uc);
            const u64 ux2  = pk2(ux,  ux);
            const u64 uxx2 = pk2(uxx, uxx);

            u64 a0 = 0ull, a1 = 0ull, a2 = 0ull, a3 = 0ull;
#pragma unroll
            for (int jj = 0; jj < JP2; jj++) {
                const int jp = jp0 + jj;
                const u64 w1u2  = ldp(W1u2  + jp);
                const u64 w1x2  = ldp(W1x2  + jp);
                const u64 w1xx2 = ldp(W1xx2 + jp);
                const u64 w22   = ldp(W2p   + jp);
                const u64 nw22  = ldp(nW2p  + jp);
                u64 pre = pre_c[jj];
                pre = fma2(uc2,  w1u2,  pre);
                pre = fma2(ux2,  w1x2,  pre);
                pre = fma2(uxx2, w1xx2, pre);
                const float2 pf = upk2(pre);
                const u64 t2 = pk2(tanh_fast(pf.x), tanh_fast(pf.y));
                a0 = fma2(t2, w22, a0);
                const u64 tsq = mul2(t2, t2);
                const u64 g2  = fma2(tsq, nw22, w22);
                a1 = fma2(g2, w1u2,  a1);
                a2 = fma2(g2, w1x2,  a2);
                a3 = fma2(g2, w1xx2, a3);
            }
            const float2 f0 = upk2(a0), f1 = upk2(a1), f2 = upk2(a2), f3 = upk2(a3);
            float s0 = f0.x + f0.y, s1 = f1.x + f1.y, s2 = f2.x + f2.y, s3 = f3.x + f3.y;

            bar_sync_id(4);                        // wait partials from warps 4-15
            const float4 r1 = red[q + 128];
            const float4 r2 = red[q + 256];
            const float4 r3 = red[q + 384];
            const float acc_res  = (s0 + r1.x) + (r2.x + r3.x);
            const float acc_du   = (s1 + r1.y) + (r2.y + r3.y);
            const float acc_dux  = (s2 + r1.z) + (r2.z + r3.z);
            const float acc_duxx = (s3 + r1.w) + (r2.w + r3.w);

            const float qq = (acc_duxx + STAB) * inv_hfhb;
            // payload: pa=sub, prb=rcp(diag), pc_=sup, pw=rhs; own diag in my
            float pa = (i == 0)         ? 0.0f : fmaf(-acc_dux, inv_dx2, qq);
            float my = acc_du - 2.0f * qq;
            float pc_ = (i == N_INT - 1) ? 0.0f : fmaf( acc_dux, inv_dx2, qq);
            float pw = acc_res + b2s + STAB * uxx;
            float prb = frcp(my);
            T[0][i] = make_float4(pa, prb, pc_, pw);
            bar_pcr();

            // ---- shared PCR steps s=1,2 (rcp shared via payload) ----
#pragma unroll
            for (int s = 1; s <= 2; s <<= 1) {
                float4 lo = make_float4(0.f, 1.f, 0.f, 0.f);
                float4 hi = make_float4(0.f, 1.f, 0.f, 0.f);
                if (i >= s)        lo = T[s - 1][i - s];
                if (i + s < N_INT) hi = T[s - 1][i + s];
                const float alpha = -pa  * lo.y;        // -a * rb_lo (FMUL)
                const float beta  = -pc_ * hi.y;        // -c * rb_hi
                AB[s - 1][i] = make_float2(alpha, beta);
                const float na = alpha * lo.x;
                const float nc = beta  * hi.z;
                my = fmaf(alpha, lo.z, fmaf(beta, hi.x, my));
                pw = fmaf(alpha, lo.w, fmaf(beta, hi.w, pw));
                pa = na; pc_ = nc;
                prb = frcp(my);
                if (s == 1) { T[1][i] = make_float4(pa, prb, pc_, pw); bar_pcr(); }
            }

            // ---- shfl PCR steps (rcp off critical path; exact-zero edges) ----
            int st = 2;
#pragma unroll
            for (int d = 1; d <= 8; d <<= 1, st++) {
                const float loa = __shfl_up_sync(0xffffffffu, pa,  d);
                const float lor = __shfl_up_sync(0xffffffffu, prb, d);
                const float loc = __shfl_up_sync(0xffffffffu, pc_, d);
                const float low = __shfl_up_sync(0xffffffffu, pw,  d);
                const float hia = __shfl_down_sync(0xffffffffu, pa,  d);
                const float hir = __shfl_down_sync(0xffffffffu, prb, d);
                const float hic = __shfl_down_sync(0xffffffffu, pc_, d);
                const float hiw = __shfl_down_sync(0xffffffffu, pw,  d);
                const float alpha = -pa  * lor;
                const float beta  = -pc_ * hir;
                AB[st][i] = make_float2(alpha, beta);
                const float na = alpha * loa;
                const float nc = beta  * hic;
                my = fmaf(alpha, loc, fmaf(beta, hia, my));
                pw = fmaf(alpha, low, fmaf(beta, hiw, pw));
                pa = na; pc_ = nc;
                prb = frcp(my);
            }

            // ---- close: pairs (i, i^64) <-> lanes (L, L^16), 2x2 Cramer ----
            const float qa_ = __shfl_xor_sync(0xffffffffu, pa,  16);
            const float qmy = __shfl_xor_sync(0xffffffffu, my,  16);
            const float qc_ = __shfl_xor_sync(0xffffffffu, pc_, 16);
            const float qw_ = __shfl_xor_sync(0xffffffffu, pw,  16);
            const float cc = (L < 16) ? pc_ : pa;
            const float qa = (L < 16) ? qa_ : qc_;
            const float den = fmaf(my, qmy, -cc * qa);
            const float inv = frcp(den);
            KAB[i] = make_float2(qmy * inv, -cc * inv);
            const float xsol = fmaf(pw, qmy, -cc * qw_) * inv;
            us[i + 1] = uc - xsol;                           // DAMP = 1
            bar_pcr();                                       // us visible in warps 0-3
            bar_arrive_id(3);                                // release MLP warps
        }

        // ================= chord step: u5 = u4 - J(u3)^{-1} r(u4) ==========
        {
            const float um  = us[i];
            const float uc  = us[i + 1];
            const float up  = us[i + 2];
            const float ux  = (up - um) * inv_dx2;
            const float uxx = (up - 2.0f * uc + um) * inv_hfhb;
            const u64 uc2  = pk2(uc,  uc);
            const u64 ux2  = pk2(ux,  ux);
            const u64 uxx2 = pk2(uxx, uxx);

            u64 a0 = 0ull;                       // residual only
#pragma unroll
            for (int jj = 0; jj < JP2; jj++) {
                const int jp = jp0 + jj;
                u64 pre = pre_c[jj];
                pre = fma2(uc2,  ldp(W1u2  + jp), pre);
                pre = fma2(ux2,  ldp(W1x2  + jp), pre);
                pre = fma2(uxx2, ldp(W1xx2 + jp), pre);
                const float2 pf = upk2(pre);
                const u64 t2 = pk2(tanh_fast(pf.x), tanh_fast(pf.y));
                a0 = fma2(t2, ldp(W2p + jp), a0);
            }
            const float2 f0 = upk2(a0);
            float d = (f0.x + f0.y);

            bar_sync_id(4);                      // wait residual partials
            d += redf[4 * (q + 128)] + redf[4 * (q + 256)] + redf[4 * (q + 384)];
            d += b2s + STAB * uxx;               // r(u4)

            // ---- divide-free cascade through saved multipliers ----
            Td[i] = d; bar_pcr();
            {   const float2 ab = AB[0][i];
                const float dlo = (i >= 1)         ? Td[i - 1] : 0.0f;
                const float dhi = (i + 1 < N_INT)  ? Td[i + 1] : 0.0f;
                d = fmaf(ab.x, dlo, fmaf(ab.y, dhi, d));
                Td[N_INT + i] = d; bar_pcr(); }
            {   const float2 ab = AB[1][i];
                const float dlo = (i >= 2)         ? Td[N_INT + i - 2] : 0.0f;
                const float dhi = (i + 2 < N_INT)  ? Td[N_INT + i + 2] : 0.0f;
                d = fmaf(ab.x, dlo, fmaf(ab.y, dhi, d)); }
            int st = 2;
#pragma unroll
            for (int dd = 1; dd <= 8; dd <<= 1, st++) {
                const float2 ab = AB[st][i];
                const float dlo = __shfl_up_sync(0xffffffffu, d, dd);
                const float dhi = __shfl_down_sync(0xffffffffu, d, dd);
                d = fmaf(ab.x, dlo, fmaf(ab.y, dhi, d));
            }
            const float dq = __shfl_xor_sync(0xffffffffu, d, 16);
            const float2 k = KAB[i];
            out[bid * N_INT + i] = uc - fmaf(k.x, d, k.y * dq);
        }
    } else {
        // ================= MLP-only warps (tid 128..511) ====================
#pragma unroll 1
        for (int iter = 0; iter < NEWTON_ITERS; iter++) {
            if (iter) bar_sync_id(3);            // wait updated us
            const float um  = us[i];
            const float uc  = us[i + 1];
            const float up  = us[i + 2];
            const float ux  = (up - um) * inv_dx2;
            const float uxx = (up - 2.0f * uc + um) * inv_hfhb;
            const u64 uc2  = pk2(uc,  uc);
            const u64 ux2  = pk2(ux,  ux);
            const u64 uxx2 = pk2(uxx, uxx);

            u64 a0 = 0ull, a1 = 0ull, a2 = 0ull, a3 = 0ull;
#pragma unroll
            for (int jj = 0; jj < JP2; jj++) {
                const int jp = jp0 + jj;
                const u64 w1u2  = ldp(W1u2  + jp);
                const u64 w1x2  = ldp(W1x2  + jp);
                const u64 w1xx2 = ldp(W1xx2 + jp);
                const u64 w22   = ldp(W2p   + jp);
                const u64 nw22  = ldp(nW2p  + jp);
                u64 pre = pre_c[jj];
                pre = fma2(uc2,  w1u2,  pre);
                pre = fma2(ux2,  w1x2,  pre);
                pre = fma2(uxx2, w1xx2, pre);
                const float2 pf = upk2(pre);
                const u64 t2 = pk2(tanh_fast(pf.x), tanh_fast(pf.y));
                a0 = fma2(t2, w22, a0);
                const u64 tsq = mul2(t2, t2);
                const u64 g2  = fma2(tsq, nw22, w22);
                a1 = fma2(g2, w1u2,  a1);
                a2 = fma2(g2, w1x2,  a2);
                a3 = fma2(g2, w1xx2, a3);
            }
            const float2 f0 = upk2(a0), f1 = upk2(a1), f2 = upk2(a2), f3 = upk2(a3);
            red[tid] = make_float4(f0.x + f0.y, f1.x + f1.y, f2.x + f2.y, f3.x + f3.y);
            bar_arrive_id(4);                    // release solver warps
        }
        // chord residual partial (approx tanh)
        {
            bar_sync_id(3);
            const float um  = us[i];
            const float uc  = us[i + 1];
            const float up  = us[i + 2];
            const float ux  = (up - um) * inv_dx2;
            const float uxx = (up - 2.0f * uc + um) * inv_hfhb;
            const u64 uc2  = pk2(uc,  uc);
            const u64 ux2  = pk2(ux,  ux);
            const u64 uxx2 = pk2(uxx, uxx);
            u64 a0 = 0ull;
#pragma unroll
            for (int jj = 0; jj < JP2; jj++) {
                const int jp = jp0 + jj;
                u64 pre = pre_c[jj];
                pre = fma2(uc2,  ldp(W1u2  + jp), pre);
                pre = fma2(ux2,  ldp(W1x2  + jp), pre);
                pre = fma2(uxx2, ldp(W1xx2 + jp), pre);
                const float2 pf = upk2(pre);
                const u64 t2 = pk2(tanh_fast(pf.x), tanh_fast(pf.y));
                a0 = fma2(t2, ldp(W2p + jp), a0);
            }
            const float2 f0 = upk2(a0);
            redf[4 * tid] = f0.x + f0.y;
            bar_arrive_id(4);
        }
    }
}

extern "C" void kernel_launch(void* const* d_in, const int* in_sizes, int n_in,
                              void* d_out, int out_size)
{
    const float* u0 = (const float*)d_in[0];
    const float* zb = (const float*)d_in[1];
    const float* x  = (const float*)d_in[2];
    const float* W1 = (const float*)d_in[3];
    const float* b1 = (const float*)d_in[4];
    const float* W2 = (const float*)d_in[5];
    const float* b2 = (const float*)d_in[6];
    pde_newton_kernel<<<BATCH, NT>>>(u0, zb, x, W1, b1, W2, b2, (float*)d_out);
}

// round 15
// speedup vs baseline: 1.1604x; 1.0025x over previous
#include <cuda_runtime.h>
#include <math.h>

#define N_X      130
#define N_INT    128
#define BATCH    64
#define LATENT   8
#define HIDDEN   64
#define IN_DIM   12
#define STAB     0.1f
#define MAX_ITER 5                   // 5 straight Newton legs (serial-leg floor)
#define GROUPS   4
#define JPT      (HIDDEN / GROUPS)   // 16 hidden units per thread
#define JP2      (JPT / 2)           // 8 packed pairs
#define NT       (N_INT * GROUPS)    // 512 threads

typedef unsigned long long u64;
union F2U { float2 f; u64 u; };

__device__ __forceinline__ u64 pk2(float lo, float hi) {
    F2U t; t.f = make_float2(lo, hi); return t.u;
}
__device__ __forceinline__ float2 upk2(u64 v) { F2U t; t.u = v; return t.f; }
__device__ __forceinline__ u64 ldp(const float2* p) { F2U t; t.f = *p; return t.u; }

__device__ __forceinline__ u64 fma2(u64 a, u64 b, u64 c) {
    u64 d; asm("fma.rn.f32x2 %0, %1, %2, %3;" : "=l"(d) : "l"(a), "l"(b), "l"(c)); return d;
}
__device__ __forceinline__ u64 mul2(u64 a, u64 b) {
    u64 d; asm("mul.rn.f32x2 %0, %1, %2;" : "=l"(d) : "l"(a), "l"(b)); return d;
}
__device__ __forceinline__ float tanh_fast(float v) {
    float y; asm("tanh.approx.f32 %0, %1;" : "=f"(y) : "f"(v)); return y;
}
__device__ __forceinline__ float frcp(float v) {
    float y; asm("rcp.approx.f32 %0, %1;" : "=f"(y) : "f"(v)); return y;
}
__device__ __forceinline__ void bar_pcr() {                 // warps 0-3 only
    asm volatile("bar.sync 1, 128;" ::: "memory");
}
__device__ __forceinline__ void bar_sync_id(int id) {
    asm volatile("bar.sync %0, %1;" :: "r"(id), "n"(NT) : "memory");
}
__device__ __forceinline__ void bar_arrive_id(int id) {
    asm volatile("bar.arrive %0, %1;" :: "r"(id), "n"(NT) : "memory");
}

__global__ void __launch_bounds__(NT, 1)
pde_newton_kernel(const float* __restrict__ u0,
                  const float* __restrict__ zb,
                  const float* __restrict__ x,
                  const float* __restrict__ W1,
                  const float* __restrict__ b1,
                  const float* __restrict__ W2,
                  const float* __restrict__ b2,
                  float* __restrict__ out)
{
    __shared__ float  W1s[IN_DIM * HIDDEN];
    __shared__ float  b1s[HIDDEN];
    __shared__ float  W2s[HIDDEN];
    __shared__ float  nW2s[HIDDEN];
    __shared__ float  zs[LATENT];
    __shared__ float  xs[N_X];
    __shared__ float  us[N_INT + 2];        // zero Dirichlet padding
    __shared__ float4 red[NT];              // MLP partial sums
    __shared__ float4 T[2][N_INT];          // PCR payload (a, rb, c, d)
    __shared__ float  b2s;

    const int tid = threadIdx.x;
    const int bid = blockIdx.x;
    const int q   = tid & (N_INT - 1);
    const int L   = q & 31;                 // lane
    const int ws  = q >> 5;                 // subwarp 0..3
    const int i   = 4 * L + ws;             // permuted interior point:
                                            // PCR dists 4..32 are lane offsets
    const int g   = tid >> 7;               // hidden group 0..3 (warp-uniform)

    // ---- cooperative loads (W1 as float4) ----
    if (tid < (IN_DIM * HIDDEN) / 4)
        ((float4*)W1s)[tid] = ((const float4*)W1)[tid];
    if (tid < HIDDEN) { b1s[tid] = b1[tid]; W2s[tid] = W2[tid]; nW2s[tid] = -W2[tid]; }
    if (tid < LATENT) zs[tid] = zb[bid * LATENT + tid];
    if (tid < N_X)    xs[tid] = x[tid];
    if (tid == 0) { b2s = b2[0]; us[0] = 0.0f; us[N_INT + 1] = 0.0f; }
    if (tid < N_INT)  us[tid + 1] = u0[bid * N_INT + tid];
    __syncthreads();

    const float xi       = xs[i + 1];
    const float inv_dx2  = 1.0f / (xs[i + 2] - xs[i]);
    const float inv_hfhb = 1.0f / ((xs[i + 2] - xs[i + 1]) * (xs[i + 1] - xs[i]));

    const float2* __restrict__ W1u2  = (const float2*)(W1s + 1 * HIDDEN);
    const float2* __restrict__ W1x2  = (const float2*)(W1s + 2 * HIDDEN);
    const float2* __restrict__ W1xx2 = (const float2*)(W1s + 3 * HIDDEN);
    const float2* __restrict__ W2p   = (const float2*)W2s;
    const float2* __restrict__ nW2p  = (const float2*)nW2s;

    // ---- iteration-invariant preactivation (packed f32x2) ----
    const int jp0 = g * JP2;
    const u64 xi2 = pk2(xi, xi);
    u64 pre_c[JP2];
#pragma unroll
    for (int jj = 0; jj < JP2; jj++)
        pre_c[jj] = fma2(xi2, ldp((const float2*)W1s + jp0 + jj),
                              ldp((const float2*)b1s + jp0 + jj));
#pragma unroll
    for (int k = 0; k < LATENT; k++) {
        const u64 zk2 = pk2(zs[k], zs[k]);
        const float2* Wk = (const float2*)(W1s + (4 + k) * HIDDEN);
#pragma unroll
        for (int jj = 0; jj < JP2; jj++)
            pre_c[jj] = fma2(zk2, ldp(Wk + jp0 + jj), pre_c[jj]);
    }

    if (g == 0) {
        // ================= solver warps (tid 0..127) =======================
#pragma unroll 1
        for (int iter = 0; iter < MAX_ITER; iter++) {
            const bool last = (iter == MAX_ITER - 1);

            const float um  = us[i];
            const float uc  = us[i + 1];
            const float up  = us[i + 2];
            const float ux  = (up - um) * inv_dx2;
            const float uxx = (up - 2.0f * uc + um) * inv_hfhb;
            const u64 uc2  = pk2(uc,  uc);
            const u64 ux2  = pk2(ux,  ux);
            const u64 uxx2 = pk2(uxx, uxx);

            u64 a0 = 0ull, a1 = 0ull, a2 = 0ull, a3 = 0ull;
#pragma unroll
            for (int jj = 0; jj < JP2; jj++) {
                const int jp = jp0 + jj;
                const u64 w1u2  = ldp(W1u2  + jp);
                const u64 w1x2  = ldp(W1x2  + jp);
                const u64 w1xx2 = ldp(W1xx2 + jp);
                const u64 w22   = ldp(W2p   + jp);
                const u64 nw22  = ldp(nW2p  + jp);
                u64 pre = pre_c[jj];
                pre = fma2(uc2,  w1u2,  pre);
                pre = fma2(ux2,  w1x2,  pre);
                pre = fma2(uxx2, w1xx2, pre);
                const float2 pf = upk2(pre);
                const u64 t2 = pk2(tanh_fast(pf.x), tanh_fast(pf.y));
                a0 = fma2(t2, w22, a0);
                const u64 tsq = mul2(t2, t2);
                const u64 g2  = fma2(tsq, nw22, w22);   // w2*(1-t^2)
                a1 = fma2(g2, w1u2,  a1);
                a2 = fma2(g2, w1x2,  a2);
                a3 = fma2(g2, w1xx2, a3);
            }
            const float2 f0 = upk2(a0), f1 = upk2(a1), f2 = upk2(a2), f3 = upk2(a3);
            const float s0 = f0.x + f0.y, s1 = f1.x + f1.y;
            const float s2 = f2.x + f2.y, s3 = f3.x + f3.y;

            bar_sync_id(4);                        // wait partials from warps 4-15
            const float4 r1 = red[q + 128];
            const float4 r2 = red[q + 256];
            const float4 r3 = red[q + 384];
            const float acc_res  = (s0 + r1.x) + (r2.x + r3.x);
            const float acc_du   = (s1 + r1.y) + (r2.y + r3.y);
            const float acc_dux  = (s2 + r1.z) + (r2.z + r3.z);
            const float acc_duxx = (s3 + r1.w) + (r2.w + r3.w);

            const float qq = (acc_duxx + STAB) * inv_hfhb;
            // payload: pa=sub, prb=rcp(diag), pc_=sup, pw=rhs; own diag in my
            float pa  = (i == 0)         ? 0.0f : fmaf(-acc_dux, inv_dx2, qq);
            float my  = acc_du - 2.0f * qq;
            float pc_ = (i == N_INT - 1) ? 0.0f : fmaf( acc_dux, inv_dx2, qq);
            float pw  = acc_res + b2s + STAB * uxx;
            float prb = frcp(my);
            T[0][i] = make_float4(pa, prb, pc_, pw);
            bar_pcr();

            // ---- shared PCR steps s=1,2 (rcp shared via payload) ----
#pragma unroll
            for (int s = 1; s <= 2; s <<= 1) {
                float4 lo = make_float4(0.f, 1.f, 0.f, 0.f);
                float4 hi = make_float4(0.f, 1.f, 0.f, 0.f);
                if (i >= s)        lo = T[s - 1][i - s];
                if (i + s < N_INT) hi = T[s - 1][i + s];
                const float alpha = -pa  * lo.y;        // -a * rb_lo (FMUL)
                const float beta  = -pc_ * hi.y;        // -c * rb_hi
                const float na = alpha * lo.x;
                const float nc = beta  * hi.z;
                my = fmaf(alpha, lo.z, fmaf(beta, hi.x, my));
                pw = fmaf(alpha, lo.w, fmaf(beta, hi.w, pw));
                pa = na; pc_ = nc;
                prb = frcp(my);
                if (s == 1) { T[1][i] = make_float4(pa, prb, pc_, pw); bar_pcr(); }
            }

            // ---- shfl PCR steps s=4..32 (rcp off critical path) ----
            // Exact-zero edge invariant: A[i]==+-0 for i<s, C[i]==+-0 for
            // i>=N-s, so clamped-shfl garbage self-annihilates.
#pragma unroll
            for (int d = 1; d <= 8; d <<= 1) {
                const float loa = __shfl_up_sync(0xffffffffu, pa,  d);
                const float lor = __shfl_up_sync(0xffffffffu, prb, d);
                const float loc = __shfl_up_sync(0xffffffffu, pc_, d);
                const float low = __shfl_up_sync(0xffffffffu, pw,  d);
                const float hia = __shfl_down_sync(0xffffffffu, pa,  d);
                const float hir = __shfl_down_sync(0xffffffffu, prb, d);
                const float hic = __shfl_down_sync(0xffffffffu, pc_, d);
                const float hiw = __shfl_down_sync(0xffffffffu, pw,  d);
                const float alpha = -pa  * lor;
                const float beta  = -pc_ * hir;
                const float na = alpha * loa;
                const float nc = beta  * hic;
                my = fmaf(alpha, loc, fmaf(beta, hia, my));
                pw = fmaf(alpha, low, fmaf(beta, hiw, pw));
                pa = na; pc_ = nc;
                prb = frcp(my);
            }

            // ---- close: pairs (i, i^64) <-> lanes (L, L^16), 2x2 Cramer ----
            const float qa_ = __shfl_xor_sync(0xffffffffu, pa,  16);
            const float qmy = __shfl_xor_sync(0xffffffffu, my,  16);
            const float qc_ = __shfl_xor_sync(0xffffffffu, pc_, 16);
            const float qw_ = __shfl_xor_sync(0xffffffffu, pw,  16);
            const float cc = (L < 16) ? pc_ : pa;
            const float qa = (L < 16) ? qa_ : qc_;
            const float den = fmaf(my, qmy, -cc * qa);
            const float xsol = fmaf(pw, qmy, -cc * qw_) * frcp(den);
            const float unew = uc - xsol;                    // DAMP = 1
            if (last) {
                out[bid * N_INT + i] = unew;                 // fused final store
            } else {
                us[i + 1] = unew;
                bar_pcr();                                   // us visible, warps 0-3
                bar_arrive_id(3);                            // release MLP warps
            }
        }
    } else {
        // ================= MLP-only warps (tid 128..511) ====================
#pragma unroll 1
        for (int iter = 0; iter < MAX_ITER; iter++) {
            if (iter) bar_sync_id(3);            // wait updated us
            const float um  = us[i];
            const float uc  = us[i + 1];
            const float up  = us[i + 2];
            const float ux  = (up - um) * inv_dx2;
            const float uxx = (up - 2.0f * uc + um) * inv_hfhb;
            const u64 uc2  = pk2(uc,  uc);
            const u64 ux2  = pk2(ux,  ux);
            const u64 uxx2 = pk2(uxx, uxx);

            u64 a0 = 0ull, a1 = 0ull, a2 = 0ull, a3 = 0ull;
#pragma unroll
            for (int jj = 0; jj < JP2; jj++) {
                const int jp = jp0 + jj;
                const u64 w1u2  = ldp(W1u2  + jp);
                const u64 w1x2  = ldp(W1x2  + jp);
                const u64 w1xx2 = ldp(W1xx2 + jp);
                const u64 w22   = ldp(W2p   + jp);
                const u64 nw22  = ldp(nW2p  + jp);
                u64 pre = pre_c[jj];
                pre = fma2(uc2,  w1u2,  pre);
                pre = fma2(ux2,  w1x2,  pre);
                pre = fma2(uxx2, w1xx2, pre);
                const float2 pf = upk2(pre);
                const u64 t2 = pk2(tanh_fast(pf.x), tanh_fast(pf.y));
                a0 = fma2(t2, w22, a0);
                const u64 tsq = mul2(t2, t2);
                const u64 g2  = fma2(tsq, nw22, w22);
                a1 = fma2(g2, w1u2,  a1);
                a2 = fma2(g2, w1x2,  a2);
                a3 = fma2(g2, w1xx2, a3);
            }
            const float2 f0 = upk2(a0), f1 = upk2(a1), f2 = upk2(a2), f3 = upk2(a3);
            red[tid] = make_float4(f0.x + f0.y, f1.x + f1.y, f2.x + f2.y, f3.x + f3.y);
            bar_arrive_id(4);                    // release solver warps
        }
    }
}

extern "C" void kernel_launch(void* const* d_in, const int* in_sizes, int n_in,
                              void* d_out, int out_size)
{
    const float* u0 = (const float*)d_in[0];
    const float* zb = (const float*)d_in[1];
    const float* x  = (const float*)d_in[2];
    const float* W1 = (const float*)d_in[3];
    const float* b1 = (const float*)d_in[4];
    const float* W2 = (const float*)d_in[5];
    const float* b2 = (const float*)d_in[6];
    pde_newton_kernel<<<BATCH, NT>>>(u0, zb, x, W1, b1, W2, b2, (float*)d_out);
}